// round 10
// baseline (speedup 1.0000x reference)
#include <cuda_runtime.h>
#include <cuda_fp16.h>
#include <cstdint>

// Problem constants: B=32, N=1024, C=128, L=4
#define BB 32
#define NN 1024
#define CC 128
#define LL 4
#define ROWS (BB * NN)          // 32768
#define HSZ  (ROWS * CC)

// fp32 scratch
__device__ __align__(16) float g_xn[HSZ];
__device__ __align__(16) float g_hn[HSZ];
__device__ __align__(16) float g_brz[LL * 2 * CC];
// fp16 scratch
__device__ __align__(16) __half g_adjT[(size_t)BB * NN * NN];   // [b][n][j] exact
__device__ __align__(16) __half g_hwT_hi[HSZ];                  // [d][b*N+j]
__device__ __align__(16) __half g_hwT_lo[HSZ];
__device__ __align__(16) __half g_hA_hi[HSZ];                   // h splits (ping)
__device__ __align__(16) __half g_hA_lo[HSZ];
__device__ __align__(16) __half g_hB_hi[HSZ];                   // h splits (pong)
__device__ __align__(16) __half g_hB_lo[HSZ];
__device__ __align__(16) __half g_mA_hi[HSZ];                   // m splits
__device__ __align__(16) __half g_mA_lo[HSZ];
__device__ __align__(16) __half g_wT_hi[LL * CC * CC];          // [l][d][c]
__device__ __align__(16) __half g_wT_lo[LL * CC * CC];
__device__ __align__(16) __half g_wih_hi[LL * 3 * CC * CC];
__device__ __align__(16) __half g_wih_lo[LL * 3 * CC * CC];
__device__ __align__(16) __half g_whh_hi[LL * 3 * CC * CC];
__device__ __align__(16) __half g_whh_lo[LL * 3 * CC * CC];
// Brz: [l][q=interleaved rz row 0..255][k 0..255]  (k<128: w_ih, k>=128: w_hh)
__device__ __align__(16) __half g_Brz_hi[LL * 2 * CC * 2 * CC];
__device__ __align__(16) __half g_Brz_lo[LL * 2 * CC * 2 * CC];

// ===========================================================================
// helpers
// ===========================================================================
__device__ __forceinline__ uint32_t smem_u32(const void* p) {
    uint32_t a;
    asm("{ .reg .u64 t; cvta.to.shared.u64 t, %1; cvt.u32.u64 %0, t; }"
        : "=r"(a) : "l"(p));
    return a;
}
__device__ __forceinline__ void cp16(uint32_t s, const void* g) {
    asm volatile("cp.async.cg.shared.global [%0], [%1], 16;" :: "r"(s), "l"(g));
}
#define CP_COMMIT() asm volatile("cp.async.commit_group;" ::: "memory")
#define CP_WAIT(n)  asm volatile("cp.async.wait_group %0;" :: "n"(n) : "memory")

#define LDSM4(R0, R1, R2, R3, ADDR)                                          \
    asm volatile("ldmatrix.sync.aligned.m8n8.x4.shared.b16 {%0,%1,%2,%3}, [%4];" \
                 : "=r"(R0), "=r"(R1), "=r"(R2), "=r"(R3) : "r"(ADDR))

#define MMA16816(D, A, B0, B1)                                               \
    asm volatile(                                                            \
        "mma.sync.aligned.m16n8k16.row.col.f32.f16.f16.f32 "                 \
        "{%0,%1,%2,%3},{%4,%5,%6,%7},{%8,%9},{%0,%1,%2,%3};"                 \
        : "+f"((D)[0]), "+f"((D)[1]), "+f"((D)[2]), "+f"((D)[3])             \
        : "r"((A)[0]), "r"((A)[1]), "r"((A)[2]), "r"((A)[3]),                \
          "r"(B0), "r"(B1))

// Load an R-row x 64-col fp16 tile (128B rows, XOR-16B swizzle) via cp.async.
template <int R>
__device__ __forceinline__ void cp_tile(const __half* __restrict__ g,
                                        int stride, uint32_t sdst, int t, int kc)
{
    #pragma unroll
    for (int u = 0; u < R / 32; ++u) {
        const int unit = t + u * 256;
        const int row  = unit >> 3;
        const int c16  = unit & 7;
        const uint32_t sw = ((row << 7) + (c16 << 4)) ^ ((row & 7) << 4);
        cp16(sdst + sw, g + (size_t)row * stride + (kc << 6) + (c16 << 3));
    }
}

// ===========================================================================
// adj GEMM: CTA 256x128, warp 64x64, 3-stage pipeline.  (R7 verbatim)
//   C = A @ (Bhi + Blo)^T  (A exact fp16), out: fp16 hi/lo split
// ===========================================================================
__global__ __launch_bounds__(256)
void adj_mma(const __half* __restrict__ a, const __half* __restrict__ b_hi,
             const __half* __restrict__ b_lo,
             __half* __restrict__ Chi, __half* __restrict__ Clo,
             int K, int lda, int ldb, int ldc,
             long sA, long sB, long sC)
{
    constexpr uint32_t ATSZ = 32768;
    constexpr uint32_t BTSZ = 16384;
    constexpr uint32_t STG  = ATSZ + 2 * BTSZ;   // 64 KB, 3 stages = 192 KB
    extern __shared__ __align__(128) char smem[];
    const uint32_t sbase = smem_u32(smem);

    const int t     = threadIdx.x;
    const int lane  = t & 31;
    const int warp  = t >> 5;
    const int mwarp = (warp >> 1) * 64;
    const int nwarp = (warp & 1) * 64;
    const int m0 = blockIdx.y * 256;
    const int z  = blockIdx.z;

    const __half* Ag = a    + (size_t)z * sA + (size_t)m0 * lda;
    const __half* Bh = b_hi + (size_t)z * sB;
    const __half* Bl = b_lo + (size_t)z * sB;

    const int NC = K >> 6;

    float acc[4][8][4];
    #pragma unroll
    for (int i = 0; i < 4; i++)
        #pragma unroll
        for (int j = 0; j < 8; j++)
            #pragma unroll
            for (int q = 0; q < 4; q++)
                acc[i][j][q] = 0.0f;

    auto load_stage = [&](int kc, uint32_t sb) {
        cp_tile<256>(Ag, lda, sb, t, kc);
        cp_tile<128>(Bh, ldb, sb + ATSZ, t, kc);
        cp_tile<128>(Bl, ldb, sb + ATSZ + BTSZ, t, kc);
        CP_COMMIT();
    };

    load_stage(0, sbase);
    load_stage(1, sbase + STG);

    for (int c = 0; c < NC; ++c) {
        const int nxt = c + 2;
        if (nxt < NC) load_stage(nxt, sbase + (nxt % 3) * STG);
        const int nleft = NC - 1 - c;
        if (nleft >= 2)      CP_WAIT(2);
        else if (nleft == 1) CP_WAIT(1);
        else                 CP_WAIT(0);
        __syncthreads();

        const uint32_t S = sbase + (c % 3) * STG;
        const uint32_t Bb = S + ATSZ;

        #pragma unroll
        for (int ks = 0; ks < 4; ++ks) {
            uint32_t ah[4][4];
            #pragma unroll
            for (int mb = 0; mb < 4; ++mb) {
                const int row = mwarp + mb * 16 + (lane & 15);
                const int col = ks * 32 + ((lane >> 4) << 4);
                const uint32_t sw = (row << 7) + (col ^ ((row & 7) << 4));
                LDSM4(ah[mb][0], ah[mb][1], ah[mb][2], ah[mb][3], S + sw);
            }
            uint32_t bh[4][4], bl[4][4];
            #pragma unroll
            for (int nq = 0; nq < 4; ++nq) {
                const int row = nwarp + nq * 16 + ((lane >> 4) << 3) + (lane & 7);
                const int col = ks * 32 + (((lane >> 3) & 1) << 4);
                const uint32_t sw = (row << 7) + (col ^ ((row & 7) << 4));
                LDSM4(bh[nq][0], bh[nq][1], bh[nq][2], bh[nq][3], Bb + sw);
                LDSM4(bl[nq][0], bl[nq][1], bl[nq][2], bl[nq][3], Bb + BTSZ + sw);
            }
            #pragma unroll
            for (int mb = 0; mb < 4; ++mb)
                #pragma unroll
                for (int n = 0; n < 8; ++n) {
                    const int q0 = (n & 1) * 2;
                    MMA16816(acc[mb][n], ah[mb], bh[n >> 1][q0], bh[n >> 1][q0 + 1]);
                    MMA16816(acc[mb][n], ah[mb], bl[n >> 1][q0], bl[n >> 1][q0 + 1]);
                }
        }
        __syncthreads();
    }

    const int rbase = m0 + mwarp + (lane >> 2);
    const int cbase = nwarp + (lane & 3) * 2;
    __half* CH = Chi + (size_t)z * sC;
    __half* CL = Clo + (size_t)z * sC;
    #pragma unroll
    for (int mb = 0; mb < 4; ++mb) {
        #pragma unroll
        for (int n = 0; n < 8; ++n) {
            const int gc = cbase + n * 8;
            const int r  = rbase + mb * 16;
            #pragma unroll
            for (int hf = 0; hf < 2; ++hf) {
                const float v0 = acc[mb][n][hf * 2 + 0];
                const float v1 = acc[mb][n][hf * 2 + 1];
                const __half h0 = __float2half_rn(v0);
                const __half h1 = __float2half_rn(v1);
                __half2 ph; ph.x = h0; ph.y = h1;
                __half2 pl;
                pl.x = __float2half_rn(v0 - __half2float(h0));
                pl.y = __float2half_rn(v1 - __half2float(h1));
                const size_t off = (size_t)(r + hf * 8) * ldc + gc;
                *reinterpret_cast<__half2*>(&CH[off]) = ph;
                *reinterpret_cast<__half2*>(&CL[off]) = pl;
            }
        }
    }
}

// ===========================================================================
// gate_n: merged xn/hn GEMMs (grid.z selects set). 3-product, fp32 out.
//   z=0: xn = m @ w_ih_n^T + b_ih_n ; z=1: hn = h @ w_hh_n^T + b_hh_n
// CTA 256x128, K=128 (NC=2), ldc=128.
// ===========================================================================
__global__ __launch_bounds__(256)
void gate_n(const __half* __restrict__ a0h, const __half* __restrict__ a0l,
            const __half* __restrict__ b0h, const __half* __restrict__ b0l,
            float* __restrict__ C0, const float* __restrict__ bias0,
            const __half* __restrict__ a1h, const __half* __restrict__ a1l,
            const __half* __restrict__ b1h, const __half* __restrict__ b1l,
            float* __restrict__ C1, const float* __restrict__ bias1)
{
    constexpr uint32_t ATSZ = 32768;
    constexpr uint32_t BTSZ = 16384;
    constexpr uint32_t STG  = 2 * ATSZ + 2 * BTSZ;   // 96 KB, 2 stages
    extern __shared__ __align__(128) char smem[];
    const uint32_t sbase = smem_u32(smem);

    const int t     = threadIdx.x;
    const int lane  = t & 31;
    const int warp  = t >> 5;
    const int mwarp = (warp >> 1) * 64;
    const int nwarp = (warp & 1) * 64;
    const int m0 = blockIdx.y * 256;
    const int z  = blockIdx.z;

    const __half* Ah = (z == 0 ? a0h : a1h) + (size_t)m0 * CC;
    const __half* Al = (z == 0 ? a0l : a1l) + (size_t)m0 * CC;
    const __half* Bh = (z == 0 ? b0h : b1h);
    const __half* Bl = (z == 0 ? b0l : b1l);
    float* C = (z == 0 ? C0 : C1);
    const float* bias = (z == 0 ? bias0 : bias1);

    constexpr int NC = 2;

    float acc[4][8][4];
    #pragma unroll
    for (int i = 0; i < 4; i++)
        #pragma unroll
        for (int j = 0; j < 8; j++)
            #pragma unroll
            for (int q = 0; q < 4; q++)
                acc[i][j][q] = 0.0f;

    auto load_stage = [&](int kc, uint32_t sb) {
        cp_tile<256>(Ah, CC, sb, t, kc);
        cp_tile<256>(Al, CC, sb + ATSZ, t, kc);
        cp_tile<128>(Bh, CC, sb + 2 * ATSZ, t, kc);
        cp_tile<128>(Bl, CC, sb + 2 * ATSZ + BTSZ, t, kc);
        CP_COMMIT();
    };

    load_stage(0, sbase);
    load_stage(1, sbase + STG);

    #pragma unroll
    for (int c = 0; c < NC; ++c) {
        if (c == 0) CP_WAIT(1); else CP_WAIT(0);
        __syncthreads();

        const uint32_t S = sbase + c * STG;
        const uint32_t Bb = S + 2 * ATSZ;

        #pragma unroll
        for (int ks = 0; ks < 4; ++ks) {
            uint32_t ah[4][4], al[4][4];
            #pragma unroll
            for (int mb = 0; mb < 4; ++mb) {
                const int row = mwarp + mb * 16 + (lane & 15);
                const int col = ks * 32 + ((lane >> 4) << 4);
                const uint32_t sw = (row << 7) + (col ^ ((row & 7) << 4));
                LDSM4(ah[mb][0], ah[mb][1], ah[mb][2], ah[mb][3], S + sw);
                LDSM4(al[mb][0], al[mb][1], al[mb][2], al[mb][3], S + ATSZ + sw);
            }
            uint32_t bh[4][4], bl[4][4];
            #pragma unroll
            for (int nq = 0; nq < 4; ++nq) {
                const int row = nwarp + nq * 16 + ((lane >> 4) << 3) + (lane & 7);
                const int col = ks * 32 + (((lane >> 3) & 1) << 4);
                const uint32_t sw = (row << 7) + (col ^ ((row & 7) << 4));
                LDSM4(bh[nq][0], bh[nq][1], bh[nq][2], bh[nq][3], Bb + sw);
                LDSM4(bl[nq][0], bl[nq][1], bl[nq][2], bl[nq][3], Bb + BTSZ + sw);
            }
            #pragma unroll
            for (int mb = 0; mb < 4; ++mb)
                #pragma unroll
                for (int n = 0; n < 8; ++n) {
                    const int q0 = (n & 1) * 2;
                    MMA16816(acc[mb][n], ah[mb], bh[n >> 1][q0], bh[n >> 1][q0 + 1]);
                    MMA16816(acc[mb][n], ah[mb], bl[n >> 1][q0], bl[n >> 1][q0 + 1]);
                    MMA16816(acc[mb][n], al[mb], bh[n >> 1][q0], bh[n >> 1][q0 + 1]);
                }
        }
        __syncthreads();
    }

    const int rbase = m0 + mwarp + (lane >> 2);
    const int cbase = nwarp + (lane & 3) * 2;
    #pragma unroll
    for (int mb = 0; mb < 4; ++mb) {
        #pragma unroll
        for (int n = 0; n < 8; ++n) {
            const int gc = cbase + n * 8;
            const float bx = bias[gc];
            const float by = bias[gc + 1];
            const int r = rbase + mb * 16;
            float2 v0 = { acc[mb][n][0] + bx, acc[mb][n][1] + by };
            float2 v1 = { acc[mb][n][2] + bx, acc[mb][n][3] + by };
            *reinterpret_cast<float2*>(&C[(size_t)r * CC + gc])       = v0;
            *reinterpret_cast<float2*>(&C[(size_t)(r + 8) * CC + gc]) = v1;
        }
    }
}

// ===========================================================================
// gaterz_gru: prer/prez = [m|h] @ Brz^T + brz, fused GRU epilogue.
// Brz rows interleaved (r0,z0,r1,z1,...), K=256 (k<128: m-side, k>=128: h-side).
// CTA 256x128 (=64 channel-pairs), K NC=4, 2-stage.
// ===========================================================================
__global__ __launch_bounds__(256)
void gaterz_gru(const __half* __restrict__ mhi, const __half* __restrict__ mlo,
                const __half* __restrict__ hhi, const __half* __restrict__ hlo,
                const __half* __restrict__ Bhi, const __half* __restrict__ Blo,
                const float* __restrict__ brz,
                const float* __restrict__ xn, const float* __restrict__ hn,
                __half* __restrict__ nhi, __half* __restrict__ nlo,
                float* __restrict__ outF, const float* __restrict__ mask,
                int isLast)
{
    constexpr uint32_t ATSZ = 32768;
    constexpr uint32_t BTSZ = 16384;
    constexpr uint32_t STG  = 2 * ATSZ + 2 * BTSZ;   // 96 KB, 2 stages
    extern __shared__ __align__(128) char smem[];
    const uint32_t sbase = smem_u32(smem);

    const int t     = threadIdx.x;
    const int lane  = t & 31;
    const int warp  = t >> 5;
    const int mwarp = (warp >> 1) * 64;
    const int nwarp = (warp & 1) * 64;
    const int m0 = blockIdx.y * 256;
    const int n0 = blockIdx.x * 128;     // interleaved col offset (0 or 128)

    const __half* Bh = Bhi + (size_t)n0 * 256;
    const __half* Bl = Blo + (size_t)n0 * 256;

    constexpr int NC = 4;   // K = 256

    float acc[4][8][4];
    #pragma unroll
    for (int i = 0; i < 4; i++)
        #pragma unroll
        for (int j = 0; j < 8; j++)
            #pragma unroll
            for (int q = 0; q < 4; q++)
                acc[i][j][q] = 0.0f;

    auto load_stage = [&](int kc, uint32_t sb) {
        const __half* Ah = (kc < 2 ? mhi : hhi) + (size_t)m0 * CC;
        const __half* Al = (kc < 2 ? mlo : hlo) + (size_t)m0 * CC;
        cp_tile<256>(Ah, CC, sb, t, kc & 1);
        cp_tile<256>(Al, CC, sb + ATSZ, t, kc & 1);
        cp_tile<128>(Bh, 256, sb + 2 * ATSZ, t, kc);
        cp_tile<128>(Bl, 256, sb + 2 * ATSZ + BTSZ, t, kc);
        CP_COMMIT();
    };

    load_stage(0, sbase);

    for (int c = 0; c < NC; ++c) {
        if (c + 1 < NC) {
            load_stage(c + 1, sbase + ((c + 1) & 1) * STG);
            CP_WAIT(1);
        } else {
            CP_WAIT(0);
        }
        __syncthreads();

        const uint32_t S = sbase + (c & 1) * STG;
        const uint32_t Bb = S + 2 * ATSZ;

        #pragma unroll
        for (int ks = 0; ks < 4; ++ks) {
            uint32_t ah[4][4], al[4][4];
            #pragma unroll
            for (int mb = 0; mb < 4; ++mb) {
                const int row = mwarp + mb * 16 + (lane & 15);
                const int col = ks * 32 + ((lane >> 4) << 4);
                const uint32_t sw = (row << 7) + (col ^ ((row & 7) << 4));
                LDSM4(ah[mb][0], ah[mb][1], ah[mb][2], ah[mb][3], S + sw);
                LDSM4(al[mb][0], al[mb][1], al[mb][2], al[mb][3], S + ATSZ + sw);
            }
            uint32_t bh[4][4], bl[4][4];
            #pragma unroll
            for (int nq = 0; nq < 4; ++nq) {
                const int row = nwarp + nq * 16 + ((lane >> 4) << 3) + (lane & 7);
                const int col = ks * 32 + (((lane >> 3) & 1) << 4);
                const uint32_t sw = (row << 7) + (col ^ ((row & 7) << 4));
                LDSM4(bh[nq][0], bh[nq][1], bh[nq][2], bh[nq][3], Bb + sw);
                LDSM4(bl[nq][0], bl[nq][1], bl[nq][2], bl[nq][3], Bb + BTSZ + sw);
            }
            #pragma unroll
            for (int mb = 0; mb < 4; ++mb)
                #pragma unroll
                for (int n = 0; n < 8; ++n) {
                    const int q0 = (n & 1) * 2;
                    MMA16816(acc[mb][n], ah[mb], bh[n >> 1][q0], bh[n >> 1][q0 + 1]);
                    MMA16816(acc[mb][n], ah[mb], bl[n >> 1][q0], bl[n >> 1][q0 + 1]);
                    MMA16816(acc[mb][n], al[mb], bh[n >> 1][q0], bh[n >> 1][q0 + 1]);
                }
        }
        __syncthreads();
    }

    // ---- fused GRU epilogue ----
    const int rbase = m0 + mwarp + (lane >> 2);
    const int cbase = n0 + nwarp + (lane & 3) * 2;   // even interleaved col
    #pragma unroll
    for (int mb = 0; mb < 4; ++mb) {
        #pragma unroll
        for (int n = 0; n < 8; ++n) {
            const int gc = cbase + n * 8;   // even: (r,z) pair for channel gc>>1
            const int ch = gc >> 1;
            const float br = brz[gc];
            const float bz = brz[gc + 1];
            #pragma unroll
            for (int hf = 0; hf < 2; ++hf) {
                const int row = rbase + mb * 16 + hf * 8;
                const size_t idx = (size_t)row * CC + ch;
                const float prer = acc[mb][n][hf * 2 + 0] + br;
                const float prez = acc[mb][n][hf * 2 + 1] + bz;
                const float xnv = xn[idx];
                const float hnv = hn[idx];
                const float hv  = __half2float(hhi[idx]) + __half2float(hlo[idx]);
                const float rg = 1.0f / (1.0f + __expf(-prer));
                const float zg = 1.0f / (1.0f + __expf(-prez));
                const float ng = tanhf(xnv + rg * hnv);
                const float hnew = (1.0f - zg) * ng + zg * hv;
                if (isLast) {
                    outF[idx] = hnew * mask[row];
                } else {
                    const __half hb = __float2half_rn(hnew);
                    nhi[idx] = hb;
                    nlo[idx] = __float2half_rn(hnew - __half2float(hb));
                }
            }
        }
    }
}

// ===========================================================================
// wmma2_hw (128x128 CTA): 3-product fp16 split GEMM for hw.  (R7 verbatim)
// ===========================================================================
__global__ __launch_bounds__(256)
void wmma2_hw(const __half* __restrict__ a_hi, const __half* __restrict__ a_lo,
              const __half* __restrict__ b_hi, const __half* __restrict__ b_lo,
              __half* __restrict__ Chi, __half* __restrict__ Clo,
              int K, int lda, int ldb, int ldc)
{
    constexpr uint32_t TSZ = 16384;
    constexpr uint32_t STG = 4 * TSZ;
    extern __shared__ __align__(128) char smem[];
    const uint32_t sbase = smem_u32(smem);

    const int t     = threadIdx.x;
    const int lane  = t & 31;
    const int warp  = t >> 5;
    const int mwarp = (warp >> 1) * 32;
    const int nwarp = (warp & 1) * 64;
    const int m0 = blockIdx.y * 128;
    const int n0 = blockIdx.x * 128;

    const __half* Ah = a_hi + (size_t)m0 * lda;
    const __half* Al = a_lo + (size_t)m0 * lda;
    const __half* Bh = b_hi + (size_t)n0 * ldb;
    const __half* Bl = b_lo + (size_t)n0 * ldb;

    const int NC = K >> 6;

    float acc[2][8][4];
    #pragma unroll
    for (int i = 0; i < 2; i++)
        #pragma unroll
        for (int j = 0; j < 8; j++)
            #pragma unroll
            for (int q = 0; q < 4; q++)
                acc[i][j][q] = 0.0f;

    auto load_stage = [&](int kc, uint32_t sb) {
        cp_tile<128>(Ah, lda, sb, t, kc);
        cp_tile<128>(Al, lda, sb + TSZ, t, kc);
        cp_tile<128>(Bh, ldb, sb + 2 * TSZ, t, kc);
        cp_tile<128>(Bl, ldb, sb + 3 * TSZ, t, kc);
        CP_COMMIT();
    };

    load_stage(0, sbase);

    for (int c = 0; c < NC; ++c) {
        const int buf = c & 1;
        if (c + 1 < NC) {
            load_stage(c + 1, sbase + ((c + 1) & 1) * STG);
            CP_WAIT(1);
        } else {
            CP_WAIT(0);
        }
        __syncthreads();

        const uint32_t S = sbase + buf * STG;

        #pragma unroll
        for (int ks = 0; ks < 4; ++ks) {
            uint32_t ah[2][4], al[2][4];
            #pragma unroll
            for (int mb = 0; mb < 2; ++mb) {
                const int row = mwarp + mb * 16 + (lane & 15);
                const int col = ks * 32 + ((lane >> 4) << 4);
                const uint32_t sw = (row << 7) + (col ^ ((row & 7) << 4));
                LDSM4(ah[mb][0], ah[mb][1], ah[mb][2], ah[mb][3], S + sw);
                LDSM4(al[mb][0], al[mb][1], al[mb][2], al[mb][3], S + TSZ + sw);
            }
            uint32_t bh[4][4], bl[4][4];
            #pragma unroll
            for (int nq = 0; nq < 4; ++nq) {
                const int row = nwarp + nq * 16 + ((lane >> 4) << 3) + (lane & 7);
                const int col = ks * 32 + (((lane >> 3) & 1) << 4);
                const uint32_t sw = (row << 7) + (col ^ ((row & 7) << 4));
                LDSM4(bh[nq][0], bh[nq][1], bh[nq][2], bh[nq][3], S + 2 * TSZ + sw);
                LDSM4(bl[nq][0], bl[nq][1], bl[nq][2], bl[nq][3], S + 3 * TSZ + sw);
            }
            #pragma unroll
            for (int mb = 0; mb < 2; ++mb)
                #pragma unroll
                for (int n = 0; n < 8; ++n) {
                    const int q0 = (n & 1) * 2;
                    MMA16816(acc[mb][n], ah[mb], bh[n >> 1][q0], bh[n >> 1][q0 + 1]);
                    MMA16816(acc[mb][n], ah[mb], bl[n >> 1][q0], bl[n >> 1][q0 + 1]);
                    MMA16816(acc[mb][n], al[mb], bh[n >> 1][q0], bh[n >> 1][q0 + 1]);
                }
        }
        __syncthreads();
    }

    const int rbase = m0 + mwarp + (lane >> 2);
    const int cbase = n0 + nwarp + (lane & 3) * 2;
    #pragma unroll
    for (int mb = 0; mb < 2; ++mb) {
        #pragma unroll
        for (int n = 0; n < 8; ++n) {
            const int gc = cbase + n * 8;
            const int r  = rbase + mb * 16;
            #pragma unroll
            for (int hf = 0; hf < 2; ++hf) {
                const float v0 = acc[mb][n][hf * 2 + 0];
                const float v1 = acc[mb][n][hf * 2 + 1];
                const __half h0 = __float2half_rn(v0);
                const __half h1 = __float2half_rn(v1);
                __half2 ph; ph.x = h0; ph.y = h1;
                __half2 pl;
                pl.x = __float2half_rn(v0 - __half2float(h0));
                pl.y = __float2half_rn(v1 - __half2float(h1));
                const size_t off = (size_t)(r + hf * 8) * ldc + gc;
                *reinterpret_cast<__half2*>(&Chi[off]) = ph;
                *reinterpret_cast<__half2*>(&Clo[off]) = pl;
            }
        }
    }
}

// ===========================================================================
// Prep kernels
// ===========================================================================
__global__ __launch_bounds__(256)
void adj_transpose(const float* __restrict__ adj, __half* __restrict__ adjT)
{
    __shared__ float tile[32][33];
    const int b  = blockIdx.z;
    const int j0 = blockIdx.x * 32;
    const int n0 = blockIdx.y * 32;
    const float* src = adj + (size_t)b * NN * NN;
    __half* dst = adjT + (size_t)b * NN * NN;
    const int tx = threadIdx.x & 31, ty = threadIdx.x >> 5;
    #pragma unroll
    for (int r = ty; r < 32; r += 8)
        tile[r][tx] = src[(size_t)(j0 + r) * NN + n0 + tx];
    __syncthreads();
    #pragma unroll
    for (int r = ty; r < 32; r += 8)
        dst[(size_t)(n0 + r) * NN + j0 + tx] = __float2half_rn(tile[tx][r]);
}

__global__ __launch_bounds__(256)
void split2(const float* __restrict__ x,
            __half* __restrict__ hi, __half* __restrict__ lo)
{
    const int i = blockIdx.x * blockDim.x + threadIdx.x;
    const float v = x[i];
    const __half h = __float2half_rn(v);
    hi[i] = h;
    lo[i] = __float2half_rn(v - __half2float(h));
}

// weight[l] fp32 [C][C] (W[c][d]) -> WT hi/lo fp16 [l][d][c]
__global__ __launch_bounds__(256)
void wT_split(const float* __restrict__ W,
              __half* __restrict__ hi, __half* __restrict__ lo)
{
    __shared__ float tile[32][33];
    const int l  = blockIdx.z;
    const int c0 = blockIdx.x * 32;
    const int d0 = blockIdx.y * 32;
    const float* src = W + (size_t)l * CC * CC;
    const size_t ob = (size_t)l * CC * CC;
    const int tx = threadIdx.x & 31, ty = threadIdx.x >> 5;
    #pragma unroll
    for (int r = ty; r < 32; r += 8)
        tile[r][tx] = src[(size_t)(c0 + r) * CC + d0 + tx];
    __syncthreads();
    #pragma unroll
    for (int r = ty; r < 32; r += 8) {
        const float v = tile[tx][r];
        const __half h = __float2half_rn(v);
        hi[ob + (size_t)(d0 + r) * CC + c0 + tx] = h;
        lo[ob + (size_t)(d0 + r) * CC + c0 + tx] = __float2half_rn(v - __half2float(h));
    }
}

// Brz[l][q][k]: q interleaved (r0,z0,r1,z1,...), k<128: w_ih, k>=128: w_hh.
__global__ __launch_bounds__(256)
void brz_prep(const float* __restrict__ w_ih, const float* __restrict__ w_hh,
              __half* __restrict__ Bhi, __half* __restrict__ Blo)
{
    const int l = blockIdx.z;
    const int idx = blockIdx.x * 256 + threadIdx.x;   // < 256*256
    const int q = idx >> 8;
    const int k = idx & 255;
    const int grow = (q >> 1) + (q & 1) * CC;         // gate row in [0,256)
    float v;
    if (k < CC) v = w_ih[(size_t)l * 3 * CC * CC + (size_t)grow * CC + k];
    else        v = w_hh[(size_t)l * 3 * CC * CC + (size_t)grow * CC + (k - CC)];
    const __half h = __float2half_rn(v);
    const size_t o = (size_t)l * 256 * 256 + idx;
    Bhi[o] = h;
    Blo[o] = __float2half_rn(v - __half2float(h));
}

// brz bias: brz[l][q] = b_ih[l][grow] + b_hh[l][grow]
__global__ __launch_bounds__(256)
void brz_bias(const float* __restrict__ b_ih, const float* __restrict__ b_hh,
              float* __restrict__ brz)
{
    const int i = blockIdx.x * 256 + threadIdx.x;     // < LL*256
    const int l = i >> 8;
    const int q = i & 255;
    const int grow = (q >> 1) + (q & 1) * CC;
    brz[i] = b_ih[(size_t)l * 3 * CC + grow] + b_hh[(size_t)l * 3 * CC + grow];
}

// ===========================================================================
#define SMEM_ADJ   (3 * (32768 + 2 * 16384))         // 192 KB (3 stages)
#define SMEM_GATE  (2 * (2 * 32768 + 2 * 16384))     // 192 KB (2 stages)
#define SMEM_HW    (2 * 4 * 16384)                   // 128 KB

extern "C" void kernel_launch(void* const* d_in, const int* in_sizes, int n_in,
                              void* d_out, int out_size)
{
    const float* x      = (const float*)d_in[0];
    const float* adj    = (const float*)d_in[1];
    const float* mask   = (const float*)d_in[2];
    const float* weight = (const float*)d_in[3];
    const float* w_ih   = (const float*)d_in[4];
    const float* w_hh   = (const float*)d_in[5];
    const float* b_ih   = (const float*)d_in[6];
    const float* b_hh   = (const float*)d_in[7];
    float* out = (float*)d_out;

    float *p_xn, *p_hn, *p_brz;
    __half *p_adjT, *p_hwhi, *p_hwlo, *p_mhi, *p_mlo;
    __half *p_hAhi, *p_hAlo, *p_hBhi, *p_hBlo;
    __half *p_wThi, *p_wTlo, *p_wihhi, *p_wihlo, *p_whhhi, *p_whhlo;
    __half *p_Bhi, *p_Blo;
    cudaGetSymbolAddress((void**)&p_xn, g_xn);
    cudaGetSymbolAddress((void**)&p_hn, g_hn);
    cudaGetSymbolAddress((void**)&p_brz, g_brz);
    cudaGetSymbolAddress((void**)&p_adjT, g_adjT);
    cudaGetSymbolAddress((void**)&p_hwhi, g_hwT_hi);
    cudaGetSymbolAddress((void**)&p_hwlo, g_hwT_lo);
    cudaGetSymbolAddress((void**)&p_mhi, g_mA_hi);
    cudaGetSymbolAddress((void**)&p_mlo, g_mA_lo);
    cudaGetSymbolAddress((void**)&p_hAhi, g_hA_hi);
    cudaGetSymbolAddress((void**)&p_hAlo, g_hA_lo);
    cudaGetSymbolAddress((void**)&p_hBhi, g_hB_hi);
    cudaGetSymbolAddress((void**)&p_hBlo, g_hB_lo);
    cudaGetSymbolAddress((void**)&p_wThi, g_wT_hi);
    cudaGetSymbolAddress((void**)&p_wTlo, g_wT_lo);
    cudaGetSymbolAddress((void**)&p_wihhi, g_wih_hi);
    cudaGetSymbolAddress((void**)&p_wihlo, g_wih_lo);
    cudaGetSymbolAddress((void**)&p_whhhi, g_whh_hi);
    cudaGetSymbolAddress((void**)&p_whhlo, g_whh_lo);
    cudaGetSymbolAddress((void**)&p_Bhi, g_Brz_hi);
    cudaGetSymbolAddress((void**)&p_Blo, g_Brz_lo);

    cudaFuncSetAttribute(adj_mma,    cudaFuncAttributeMaxDynamicSharedMemorySize, SMEM_ADJ);
    cudaFuncSetAttribute(gate_n,     cudaFuncAttributeMaxDynamicSharedMemorySize, SMEM_GATE);
    cudaFuncSetAttribute(gaterz_gru, cudaFuncAttributeMaxDynamicSharedMemorySize, SMEM_GATE);
    cudaFuncSetAttribute(wmma2_hw,   cudaFuncAttributeMaxDynamicSharedMemorySize, SMEM_HW);

    // ---- once per call ----
    adj_transpose<<<dim3(NN / 32, NN / 32, BB), 256>>>(adj, p_adjT);
    wT_split<<<dim3(CC / 32, CC / 32, LL), 256>>>(weight, p_wThi, p_wTlo);
    split2<<<(LL * 3 * CC * CC) / 256, 256>>>(w_ih, p_wihhi, p_wihlo);
    split2<<<(LL * 3 * CC * CC) / 256, 256>>>(w_hh, p_whhhi, p_whhlo);
    brz_prep<<<dim3(256 * 256 / 256, 1, LL), 256>>>(w_ih, w_hh, p_Bhi, p_Blo);
    brz_bias<<<LL, 256>>>(b_ih, b_hh, p_brz);
    split2<<<HSZ / 256, 256>>>(x, p_hAhi, p_hAlo);   // h0 = x

    __half* hs_hi[2] = { p_hAhi, p_hBhi };
    __half* hs_lo[2] = { p_hAlo, p_hBlo };

    for (int l = 0; l < LL; l++) {
        __half* chi = hs_hi[l & 1];
        __half* clo = hs_lo[l & 1];
        __half* nhi = hs_hi[(l + 1) & 1];
        __half* nlo = hs_lo[(l + 1) & 1];
        const long loffW = (long)l * CC * CC;
        const long loffG = (long)l * 3 * CC * CC;

        // 1) hwT[d][b*N+j] = sum_c WT[d][c] * h[j][c]   (3-product)
        wmma2_hw<<<dim3(ROWS / 128, 1, 1), 256, SMEM_HW>>>(
            p_wThi + loffW, p_wTlo + loffW, chi, clo,
            p_hwhi, p_hwlo, CC, CC, CC, ROWS);

        // 2) m[b][n][d] = adjT[b] @ (hw_hi + hw_lo)  -> fp16 hi/lo
        adj_mma<<<dim3(1, NN / 256, BB), 256, SMEM_ADJ>>>(
            p_adjT, p_hwhi, p_hwlo, p_mhi, p_mlo,
            NN, NN, ROWS, CC,
            (long)NN * NN, (long)NN, (long)NN * CC);

        // 3) xn = m @ w_ih_n^T + b_ih_n ; hn = h @ w_hh_n^T + b_hh_n
        gate_n<<<dim3(1, ROWS / 256, 2), 256, SMEM_GATE>>>(
            p_mhi, p_mlo, p_wihhi + loffG + 2 * CC * CC, p_wihlo + loffG + 2 * CC * CC,
            p_xn, b_ih + (long)l * 3 * CC + 2 * CC,
            chi, clo, p_whhhi + loffG + 2 * CC * CC, p_whhlo + loffG + 2 * CC * CC,
            p_hn, b_hh + (long)l * 3 * CC + 2 * CC);

        // 4) prer/prez GEMM (K=256 concat) + fused GRU
        gaterz_gru<<<dim3(2, ROWS / 256), 256, SMEM_GATE>>>(
            p_mhi, p_mlo, chi, clo,
            p_Bhi + (long)l * 256 * 256, p_Blo + (long)l * 256 * 256,
            p_brz + (long)l * 256,
            p_xn, p_hn, nhi, nlo, out, mask, (l == LL - 1) ? 1 : 0);
    }
}

// round 11
// speedup vs baseline: 1.2390x; 1.2390x over previous
#include <cuda_runtime.h>
#include <cuda_fp16.h>
#include <cstdint>

// Problem constants: B=32, N=1024, C=128, L=4
#define BB 32
#define NN 1024
#define CC 128
#define LL 4
#define ROWS (BB * NN)          // 32768
#define HSZ  (ROWS * CC)
#define GSZ  (ROWS * 3 * CC)

// fp32 scratch
__device__ __align__(16) float g_gx[GSZ];
__device__ __align__(16) float g_gh[GSZ];
// fp16 scratch
__device__ __align__(16) __half g_adjT[(size_t)BB * NN * NN];   // [b][n][j] exact
__device__ __align__(16) __half g_hwT_hi[HSZ];                  // [d][b*N+j]
__device__ __align__(16) __half g_hwT_lo[HSZ];
__device__ __align__(16) __half g_hA_hi[HSZ];                   // h splits (ping)
__device__ __align__(16) __half g_hA_lo[HSZ];
__device__ __align__(16) __half g_hB_hi[HSZ];                   // h splits (pong)
__device__ __align__(16) __half g_hB_lo[HSZ];
__device__ __align__(16) __half g_mA_hi[HSZ];                   // m splits
__device__ __align__(16) __half g_mA_lo[HSZ];
__device__ __align__(16) __half g_wT_hi[LL * CC * CC];          // [l][d][c]
__device__ __align__(16) __half g_wT_lo[LL * CC * CC];
__device__ __align__(16) __half g_wih_hi[LL * 3 * CC * CC];
__device__ __align__(16) __half g_wih_lo[LL * 3 * CC * CC];
__device__ __align__(16) __half g_whh_hi[LL * 3 * CC * CC];
__device__ __align__(16) __half g_whh_lo[LL * 3 * CC * CC];

// ===========================================================================
// helpers
// ===========================================================================
__device__ __forceinline__ uint32_t smem_u32(const void* p) {
    uint32_t a;
    asm("{ .reg .u64 t; cvta.to.shared.u64 t, %1; cvt.u32.u64 %0, t; }"
        : "=r"(a) : "l"(p));
    return a;
}
__device__ __forceinline__ void cp16(uint32_t s, const void* g) {
    asm volatile("cp.async.cg.shared.global [%0], [%1], 16;" :: "r"(s), "l"(g));
}
#define CP_COMMIT() asm volatile("cp.async.commit_group;" ::: "memory")
#define CP_WAIT(n)  asm volatile("cp.async.wait_group %0;" :: "n"(n) : "memory")

#define LDSM4(R0, R1, R2, R3, ADDR)                                          \
    asm volatile("ldmatrix.sync.aligned.m8n8.x4.shared.b16 {%0,%1,%2,%3}, [%4];" \
                 : "=r"(R0), "=r"(R1), "=r"(R2), "=r"(R3) : "r"(ADDR))

#define MMA16816(D, A, B0, B1)                                               \
    asm volatile(                                                            \
        "mma.sync.aligned.m16n8k16.row.col.f32.f16.f16.f32 "                 \
        "{%0,%1,%2,%3},{%4,%5,%6,%7},{%8,%9},{%0,%1,%2,%3};"                 \
        : "+f"((D)[0]), "+f"((D)[1]), "+f"((D)[2]), "+f"((D)[3])             \
        : "r"((A)[0]), "r"((A)[1]), "r"((A)[2]), "r"((A)[3]),                \
          "r"(B0), "r"(B1))

// Load an R-row x 64-col fp16 tile (128B rows, XOR-16B swizzle) via cp.async.
template <int R>
__device__ __forceinline__ void cp_tile(const __half* __restrict__ g,
                                        int stride, uint32_t sdst, int t, int kc)
{
    #pragma unroll
    for (int u = 0; u < R / 32; ++u) {
        const int unit = t + u * 256;
        const int row  = unit >> 3;
        const int c16  = unit & 7;
        const uint32_t sw = ((row << 7) + (c16 << 4)) ^ ((row & 7) << 4);
        cp16(sdst + sw, g + (size_t)row * stride + (kc << 6) + (c16 << 3));
    }
}

// ===========================================================================
// fused adj + gh kernel.
// CTAs [0,128):   m[b][n][d] = adjT[b] @ (hw_hi+hw_lo)   (3-stage pipeline)
// CTAs [128,512): gh = h @ w_hh^T + b_hh                 (2-stage, 3-product)
// Both branches fit the same 192 KB dynamic SMEM.
// ===========================================================================
__global__ __launch_bounds__(256)
void fused_adj_gh(const __half* __restrict__ adjT,
                  const __half* __restrict__ hwhi, const __half* __restrict__ hwlo,
                  __half* __restrict__ mhi, __half* __restrict__ mlo,
                  const __half* __restrict__ hhi, const __half* __restrict__ hlo,
                  const __half* __restrict__ whh_hi, const __half* __restrict__ whh_lo,
                  float* __restrict__ gh, const float* __restrict__ bias_hh)
{
    extern __shared__ __align__(128) char smem[];
    const uint32_t sbase = smem_u32(smem);

    const int t     = threadIdx.x;
    const int lane  = t & 31;
    const int warp  = t >> 5;
    const int mwarp = (warp >> 1) * 64;
    const int nwarp = (warp & 1) * 64;

    if (blockIdx.x < 128) {
        // ================= adj branch (R7 adj_mma body) =================
        constexpr uint32_t ATSZ = 32768;
        constexpr uint32_t BTSZ = 16384;
        constexpr uint32_t STG  = ATSZ + 2 * BTSZ;   // 64 KB * 3 stages

        const int mtile = blockIdx.x & 3;
        const int z     = blockIdx.x >> 2;
        const int m0    = mtile * 256;

        const __half* Ag = adjT + (size_t)z * NN * NN + (size_t)m0 * NN;
        const __half* Bh = hwhi + (size_t)z * NN;
        const __half* Bl = hwlo + (size_t)z * NN;

        constexpr int NC = NN >> 6;   // 16

        float acc[4][8][4];
        #pragma unroll
        for (int i = 0; i < 4; i++)
            #pragma unroll
            for (int j = 0; j < 8; j++)
                #pragma unroll
                for (int q = 0; q < 4; q++)
                    acc[i][j][q] = 0.0f;

        auto load_stage = [&](int kc, uint32_t sb) {
            cp_tile<256>(Ag, NN, sb, t, kc);
            cp_tile<128>(Bh, ROWS, sb + ATSZ, t, kc);
            cp_tile<128>(Bl, ROWS, sb + ATSZ + BTSZ, t, kc);
            CP_COMMIT();
        };

        load_stage(0, sbase);
        load_stage(1, sbase + STG);

        for (int c = 0; c < NC; ++c) {
            const int nxt = c + 2;
            if (nxt < NC) load_stage(nxt, sbase + (nxt % 3) * STG);
            const int nleft = NC - 1 - c;
            if (nleft >= 2)      CP_WAIT(2);
            else if (nleft == 1) CP_WAIT(1);
            else                 CP_WAIT(0);
            __syncthreads();

            const uint32_t S = sbase + (c % 3) * STG;
            const uint32_t Bb = S + ATSZ;

            #pragma unroll
            for (int ks = 0; ks < 4; ++ks) {
                uint32_t ah[4][4];
                #pragma unroll
                for (int mb = 0; mb < 4; ++mb) {
                    const int row = mwarp + mb * 16 + (lane & 15);
                    const int col = ks * 32 + ((lane >> 4) << 4);
                    const uint32_t sw = (row << 7) + (col ^ ((row & 7) << 4));
                    LDSM4(ah[mb][0], ah[mb][1], ah[mb][2], ah[mb][3], S + sw);
                }
                uint32_t bh[4][4], bl[4][4];
                #pragma unroll
                for (int nq = 0; nq < 4; ++nq) {
                    const int row = nwarp + nq * 16 + ((lane >> 4) << 3) + (lane & 7);
                    const int col = ks * 32 + (((lane >> 3) & 1) << 4);
                    const uint32_t sw = (row << 7) + (col ^ ((row & 7) << 4));
                    LDSM4(bh[nq][0], bh[nq][1], bh[nq][2], bh[nq][3], Bb + sw);
                    LDSM4(bl[nq][0], bl[nq][1], bl[nq][2], bl[nq][3], Bb + BTSZ + sw);
                }
                #pragma unroll
                for (int mb = 0; mb < 4; ++mb)
                    #pragma unroll
                    for (int n = 0; n < 8; ++n) {
                        const int q0 = (n & 1) * 2;
                        MMA16816(acc[mb][n], ah[mb], bh[n >> 1][q0], bh[n >> 1][q0 + 1]);
                        MMA16816(acc[mb][n], ah[mb], bl[n >> 1][q0], bl[n >> 1][q0 + 1]);
                    }
            }
            __syncthreads();
        }

        const int rbase = m0 + mwarp + (lane >> 2);
        const int cbase = nwarp + (lane & 3) * 2;
        __half* CH = mhi + (size_t)z * NN * CC;
        __half* CL = mlo + (size_t)z * NN * CC;
        #pragma unroll
        for (int mb = 0; mb < 4; ++mb) {
            #pragma unroll
            for (int n = 0; n < 8; ++n) {
                const int gc = cbase + n * 8;
                const int r  = rbase + mb * 16;
                #pragma unroll
                for (int hf = 0; hf < 2; ++hf) {
                    const float v0 = acc[mb][n][hf * 2 + 0];
                    const float v1 = acc[mb][n][hf * 2 + 1];
                    const __half h0 = __float2half_rn(v0);
                    const __half h1 = __float2half_rn(v1);
                    __half2 ph; ph.x = h0; ph.y = h1;
                    __half2 pl;
                    pl.x = __float2half_rn(v0 - __half2float(h0));
                    pl.y = __float2half_rn(v1 - __half2float(h1));
                    const size_t off = (size_t)(r + hf * 8) * CC + gc;
                    *reinterpret_cast<__half2*>(&CH[off]) = ph;
                    *reinterpret_cast<__half2*>(&CL[off]) = pl;
                }
            }
        }
    } else {
        // ================= gh branch (R7 gate_mma body) =================
        constexpr uint32_t ATSZ = 32768;
        constexpr uint32_t BTSZ = 16384;
        constexpr uint32_t STG  = 2 * ATSZ + 2 * BTSZ;   // 96 KB * 2 stages

        const int id = blockIdx.x - 128;       // 0..383
        const int n0 = (id % 3) * 128;
        const int m0 = (id / 3) * 256;

        const __half* Ah = hhi + (size_t)m0 * CC;
        const __half* Al = hlo + (size_t)m0 * CC;
        const __half* Bh = whh_hi + (size_t)n0 * CC;
        const __half* Bl = whh_lo + (size_t)n0 * CC;

        constexpr int NC = 2;   // K = 128

        float acc[4][8][4];
        #pragma unroll
        for (int i = 0; i < 4; i++)
            #pragma unroll
            for (int j = 0; j < 8; j++)
                #pragma unroll
                for (int q = 0; q < 4; q++)
                    acc[i][j][q] = 0.0f;

        auto load_stage = [&](int kc, uint32_t sb) {
            cp_tile<256>(Ah, CC, sb, t, kc);
            cp_tile<256>(Al, CC, sb + ATSZ, t, kc);
            cp_tile<128>(Bh, CC, sb + 2 * ATSZ, t, kc);
            cp_tile<128>(Bl, CC, sb + 2 * ATSZ + BTSZ, t, kc);
            CP_COMMIT();
        };

        load_stage(0, sbase);
        load_stage(1, sbase + STG);

        #pragma unroll
        for (int c = 0; c < NC; ++c) {
            if (c == 0) CP_WAIT(1); else CP_WAIT(0);
            __syncthreads();

            const uint32_t S = sbase + c * STG;
            const uint32_t Bb = S + 2 * ATSZ;

            #pragma unroll
            for (int ks = 0; ks < 4; ++ks) {
                uint32_t ah[4][4], al[4][4];
                #pragma unroll
                for (int mb = 0; mb < 4; ++mb) {
                    const int row = mwarp + mb * 16 + (lane & 15);
                    const int col = ks * 32 + ((lane >> 4) << 4);
                    const uint32_t sw = (row << 7) + (col ^ ((row & 7) << 4));
                    LDSM4(ah[mb][0], ah[mb][1], ah[mb][2], ah[mb][3], S + sw);
                    LDSM4(al[mb][0], al[mb][1], al[mb][2], al[mb][3], S + ATSZ + sw);
                }
                uint32_t bh[4][4], bl[4][4];
                #pragma unroll
                for (int nq = 0; nq < 4; ++nq) {
                    const int row = nwarp + nq * 16 + ((lane >> 4) << 3) + (lane & 7);
                    const int col = ks * 32 + (((lane >> 3) & 1) << 4);
                    const uint32_t sw = (row << 7) + (col ^ ((row & 7) << 4));
                    LDSM4(bh[nq][0], bh[nq][1], bh[nq][2], bh[nq][3], Bb + sw);
                    LDSM4(bl[nq][0], bl[nq][1], bl[nq][2], bl[nq][3], Bb + BTSZ + sw);
                }
                #pragma unroll
                for (int mb = 0; mb < 4; ++mb)
                    #pragma unroll
                    for (int n = 0; n < 8; ++n) {
                        const int q0 = (n & 1) * 2;
                        MMA16816(acc[mb][n], ah[mb], bh[n >> 1][q0], bh[n >> 1][q0 + 1]);
                        MMA16816(acc[mb][n], ah[mb], bl[n >> 1][q0], bl[n >> 1][q0 + 1]);
                        MMA16816(acc[mb][n], al[mb], bh[n >> 1][q0], bh[n >> 1][q0 + 1]);
                    }
            }
            __syncthreads();
        }

        const int rbase = m0 + mwarp + (lane >> 2);
        const int cbase = n0 + nwarp + (lane & 3) * 2;
        #pragma unroll
        for (int mb = 0; mb < 4; ++mb) {
            #pragma unroll
            for (int n = 0; n < 8; ++n) {
                const int gc = cbase + n * 8;
                const float bx = bias_hh[gc];
                const float by = bias_hh[gc + 1];
                const int r = rbase + mb * 16;
                float2 v0 = { acc[mb][n][0] + bx, acc[mb][n][1] + by };
                float2 v1 = { acc[mb][n][2] + bx, acc[mb][n][3] + by };
                *reinterpret_cast<float2*>(&gh[(size_t)r * (3 * CC) + gc])       = v0;
                *reinterpret_cast<float2*>(&gh[(size_t)(r + 8) * (3 * CC) + gc]) = v1;
            }
        }
    }
}

// ===========================================================================
// gate_mma: gx = m @ w_ih^T + b_ih  (3-product, fp32 out, ldc=384)
// CTA 256x128, warp 64x64, 2-stage. K=128 (NC=2).
// ===========================================================================
__global__ __launch_bounds__(256)
void gate_mma(const __half* __restrict__ a_hi, const __half* __restrict__ a_lo,
              const __half* __restrict__ b_hi, const __half* __restrict__ b_lo,
              float* __restrict__ C, const float* __restrict__ bias)
{
    constexpr uint32_t ATSZ = 32768;
    constexpr uint32_t BTSZ = 16384;
    constexpr uint32_t STG  = 2 * ATSZ + 2 * BTSZ;   // 96 KB, 2 stages
    extern __shared__ __align__(128) char smem[];
    const uint32_t sbase = smem_u32(smem);

    const int t     = threadIdx.x;
    const int lane  = t & 31;
    const int warp  = t >> 5;
    const int mwarp = (warp >> 1) * 64;
    const int nwarp = (warp & 1) * 64;
    const int m0 = blockIdx.y * 256;
    const int n0 = blockIdx.x * 128;

    const __half* Ah = a_hi + (size_t)m0 * CC;
    const __half* Al = a_lo + (size_t)m0 * CC;
    const __half* Bh = b_hi + (size_t)n0 * CC;
    const __half* Bl = b_lo + (size_t)n0 * CC;

    constexpr int NC = 2;

    float acc[4][8][4];
    #pragma unroll
    for (int i = 0; i < 4; i++)
        #pragma unroll
        for (int j = 0; j < 8; j++)
            #pragma unroll
            for (int q = 0; q < 4; q++)
                acc[i][j][q] = 0.0f;

    auto load_stage = [&](int kc, uint32_t sb) {
        cp_tile<256>(Ah, CC, sb, t, kc);
        cp_tile<256>(Al, CC, sb + ATSZ, t, kc);
        cp_tile<128>(Bh, CC, sb + 2 * ATSZ, t, kc);
        cp_tile<128>(Bl, CC, sb + 2 * ATSZ + BTSZ, t, kc);
        CP_COMMIT();
    };

    load_stage(0, sbase);
    load_stage(1, sbase + STG);

    #pragma unroll
    for (int c = 0; c < NC; ++c) {
        if (c == 0) CP_WAIT(1); else CP_WAIT(0);
        __syncthreads();

        const uint32_t S = sbase + c * STG;
        const uint32_t Bb = S + 2 * ATSZ;

        #pragma unroll
        for (int ks = 0; ks < 4; ++ks) {
            uint32_t ah[4][4], al[4][4];
            #pragma unroll
            for (int mb = 0; mb < 4; ++mb) {
                const int row = mwarp + mb * 16 + (lane & 15);
                const int col = ks * 32 + ((lane >> 4) << 4);
                const uint32_t sw = (row << 7) + (col ^ ((row & 7) << 4));
                LDSM4(ah[mb][0], ah[mb][1], ah[mb][2], ah[mb][3], S + sw);
                LDSM4(al[mb][0], al[mb][1], al[mb][2], al[mb][3], S + ATSZ + sw);
            }
            uint32_t bh[4][4], bl[4][4];
            #pragma unroll
            for (int nq = 0; nq < 4; ++nq) {
                const int row = nwarp + nq * 16 + ((lane >> 4) << 3) + (lane & 7);
                const int col = ks * 32 + (((lane >> 3) & 1) << 4);
                const uint32_t sw = (row << 7) + (col ^ ((row & 7) << 4));
                LDSM4(bh[nq][0], bh[nq][1], bh[nq][2], bh[nq][3], Bb + sw);
                LDSM4(bl[nq][0], bl[nq][1], bl[nq][2], bl[nq][3], Bb + BTSZ + sw);
            }
            #pragma unroll
            for (int mb = 0; mb < 4; ++mb)
                #pragma unroll
                for (int n = 0; n < 8; ++n) {
                    const int q0 = (n & 1) * 2;
                    MMA16816(acc[mb][n], ah[mb], bh[n >> 1][q0], bh[n >> 1][q0 + 1]);
                    MMA16816(acc[mb][n], ah[mb], bl[n >> 1][q0], bl[n >> 1][q0 + 1]);
                    MMA16816(acc[mb][n], al[mb], bh[n >> 1][q0], bh[n >> 1][q0 + 1]);
                }
        }
        __syncthreads();
    }

    const int rbase = m0 + mwarp + (lane >> 2);
    const int cbase = n0 + nwarp + (lane & 3) * 2;
    #pragma unroll
    for (int mb = 0; mb < 4; ++mb) {
        #pragma unroll
        for (int n = 0; n < 8; ++n) {
            const int gc = cbase + n * 8;
            const float bx = bias[gc];
            const float by = bias[gc + 1];
            const int r = rbase + mb * 16;
            float2 v0 = { acc[mb][n][0] + bx, acc[mb][n][1] + by };
            float2 v1 = { acc[mb][n][2] + bx, acc[mb][n][3] + by };
            *reinterpret_cast<float2*>(&C[(size_t)r * (3 * CC) + gc])       = v0;
            *reinterpret_cast<float2*>(&C[(size_t)(r + 8) * (3 * CC) + gc]) = v1;
        }
    }
}

// ===========================================================================
// wmma2_hw (128x128 CTA): 3-product fp16 split GEMM for hw (near-exact).
// C = Ahi@Bhi + Ahi@Blo + Alo@Bhi  -> fp16 hi/lo out (transposed layout)
// ===========================================================================
__global__ __launch_bounds__(256)
void wmma2_hw(const __half* __restrict__ a_hi, const __half* __restrict__ a_lo,
              const __half* __restrict__ b_hi, const __half* __restrict__ b_lo,
              __half* __restrict__ Chi, __half* __restrict__ Clo,
              int K, int lda, int ldb, int ldc)
{
    constexpr uint32_t TSZ = 16384;
    constexpr uint32_t STG = 4 * TSZ;
    extern __shared__ __align__(128) char smem[];
    const uint32_t sbase = smem_u32(smem);

    const int t     = threadIdx.x;
    const int lane  = t & 31;
    const int warp  = t >> 5;
    const int mwarp = (warp >> 1) * 32;
    const int nwarp = (warp & 1) * 64;
    const int m0 = blockIdx.y * 128;
    const int n0 = blockIdx.x * 128;

    const __half* Ah = a_hi + (size_t)m0 * lda;
    const __half* Al = a_lo + (size_t)m0 * lda;
    const __half* Bh = b_hi + (size_t)n0 * ldb;
    const __half* Bl = b_lo + (size_t)n0 * ldb;

    const int NC = K >> 6;

    float acc[2][8][4];
    #pragma unroll
    for (int i = 0; i < 2; i++)
        #pragma unroll
        for (int j = 0; j < 8; j++)
            #pragma unroll
            for (int q = 0; q < 4; q++)
                acc[i][j][q] = 0.0f;

    auto load_stage = [&](int kc, uint32_t sb) {
        cp_tile<128>(Ah, lda, sb, t, kc);
        cp_tile<128>(Al, lda, sb + TSZ, t, kc);
        cp_tile<128>(Bh, ldb, sb + 2 * TSZ, t, kc);
        cp_tile<128>(Bl, ldb, sb + 3 * TSZ, t, kc);
        CP_COMMIT();
    };

    load_stage(0, sbase);

    for (int c = 0; c < NC; ++c) {
        const int buf = c & 1;
        if (c + 1 < NC) {
            load_stage(c + 1, sbase + ((c + 1) & 1) * STG);
            CP_WAIT(1);
        } else {
            CP_WAIT(0);
        }
        __syncthreads();

        const uint32_t S = sbase + buf * STG;

        #pragma unroll
        for (int ks = 0; ks < 4; ++ks) {
            uint32_t ah[2][4], al[2][4];
            #pragma unroll
            for (int mb = 0; mb < 2; ++mb) {
                const int row = mwarp + mb * 16 + (lane & 15);
                const int col = ks * 32 + ((lane >> 4) << 4);
                const uint32_t sw = (row << 7) + (col ^ ((row & 7) << 4));
                LDSM4(ah[mb][0], ah[mb][1], ah[mb][2], ah[mb][3], S + sw);
                LDSM4(al[mb][0], al[mb][1], al[mb][2], al[mb][3], S + TSZ + sw);
            }
            uint32_t bh[4][4], bl[4][4];
            #pragma unroll
            for (int nq = 0; nq < 4; ++nq) {
                const int row = nwarp + nq * 16 + ((lane >> 4) << 3) + (lane & 7);
                const int col = ks * 32 + (((lane >> 3) & 1) << 4);
                const uint32_t sw = (row << 7) + (col ^ ((row & 7) << 4));
                LDSM4(bh[nq][0], bh[nq][1], bh[nq][2], bh[nq][3], S + 2 * TSZ + sw);
                LDSM4(bl[nq][0], bl[nq][1], bl[nq][2], bl[nq][3], S + 3 * TSZ + sw);
            }
            #pragma unroll
            for (int mb = 0; mb < 2; ++mb)
                #pragma unroll
                for (int n = 0; n < 8; ++n) {
                    const int q0 = (n & 1) * 2;
                    MMA16816(acc[mb][n], ah[mb], bh[n >> 1][q0], bh[n >> 1][q0 + 1]);
                    MMA16816(acc[mb][n], ah[mb], bl[n >> 1][q0], bl[n >> 1][q0 + 1]);
                    MMA16816(acc[mb][n], al[mb], bh[n >> 1][q0], bh[n >> 1][q0 + 1]);
                }
        }
        __syncthreads();
    }

    const int rbase = m0 + mwarp + (lane >> 2);
    const int cbase = n0 + nwarp + (lane & 3) * 2;
    #pragma unroll
    for (int mb = 0; mb < 2; ++mb) {
        #pragma unroll
        for (int n = 0; n < 8; ++n) {
            const int gc = cbase + n * 8;
            const int r  = rbase + mb * 16;
            #pragma unroll
            for (int hf = 0; hf < 2; ++hf) {
                const float v0 = acc[mb][n][hf * 2 + 0];
                const float v1 = acc[mb][n][hf * 2 + 1];
                const __half h0 = __float2half_rn(v0);
                const __half h1 = __float2half_rn(v1);
                __half2 ph; ph.x = h0; ph.y = h1;
                __half2 pl;
                pl.x = __float2half_rn(v0 - __half2float(h0));
                pl.y = __float2half_rn(v1 - __half2float(h1));
                const size_t off = (size_t)(r + hf * 8) * ldc + gc;
                *reinterpret_cast<__half2*>(&Chi[off]) = ph;
                *reinterpret_cast<__half2*>(&Clo[off]) = pl;
            }
        }
    }
}

// ===========================================================================
// Prep kernels
// ===========================================================================
__global__ __launch_bounds__(256)
void adj_transpose(const float* __restrict__ adj, __half* __restrict__ adjT)
{
    __shared__ float tile[32][33];
    const int b  = blockIdx.z;
    const int j0 = blockIdx.x * 32;
    const int n0 = blockIdx.y * 32;
    const float* src = adj + (size_t)b * NN * NN;
    __half* dst = adjT + (size_t)b * NN * NN;
    const int tx = threadIdx.x & 31, ty = threadIdx.x >> 5;
    #pragma unroll
    for (int r = ty; r < 32; r += 8)
        tile[r][tx] = src[(size_t)(j0 + r) * NN + n0 + tx];
    __syncthreads();
    #pragma unroll
    for (int r = ty; r < 32; r += 8)
        dst[(size_t)(n0 + r) * NN + j0 + tx] = __float2half_rn(tile[tx][r]);
}

__global__ __launch_bounds__(256)
void split2(const float* __restrict__ x,
            __half* __restrict__ hi, __half* __restrict__ lo)
{
    const int i = blockIdx.x * blockDim.x + threadIdx.x;
    const float v = x[i];
    const __half h = __float2half_rn(v);
    hi[i] = h;
    lo[i] = __float2half_rn(v - __half2float(h));
}

// weight[l] fp32 [C][C] (W[c][d]) -> WT hi/lo fp16 [l][d][c]
__global__ __launch_bounds__(256)
void wT_split(const float* __restrict__ W,
              __half* __restrict__ hi, __half* __restrict__ lo)
{
    __shared__ float tile[32][33];
    const int l  = blockIdx.z;
    const int c0 = blockIdx.x * 32;
    const int d0 = blockIdx.y * 32;
    const float* src = W + (size_t)l * CC * CC;
    const size_t ob = (size_t)l * CC * CC;
    const int tx = threadIdx.x & 31, ty = threadIdx.x >> 5;
    #pragma unroll
    for (int r = ty; r < 32; r += 8)
        tile[r][tx] = src[(size_t)(c0 + r) * CC + d0 + tx];
    __syncthreads();
    #pragma unroll
    for (int r = ty; r < 32; r += 8) {
        const float v = tile[tx][r];
        const __half h = __float2half_rn(v);
        hi[ob + (size_t)(d0 + r) * CC + c0 + tx] = h;
        lo[ob + (size_t)(d0 + r) * CC + c0 + tx] = __float2half_rn(v - __half2float(h));
    }
}

// ===========================================================================
// Fused GRU elementwise: h stored as fp16 hi/lo splits only (streaming).
// ===========================================================================
__global__ __launch_bounds__(256)
void gru_elem3(const float* __restrict__ gx, const float* __restrict__ gh,
               const __half* __restrict__ hhi_in, const __half* __restrict__ hlo_in,
               __half* __restrict__ hhi_out, __half* __restrict__ hlo_out,
               float* __restrict__ outF,
               const float* __restrict__ mask, int isLast)
{
    const int idx = blockIdx.x * blockDim.x + threadIdx.x;
    const int r = idx >> 7;
    const int c = idx & 127;

    const long gbase = (long)r * (3 * CC);
    const float xr = gx[gbase + c];
    const float xz = gx[gbase + CC + c];
    const float xn = gx[gbase + 2 * CC + c];
    const float hr = gh[gbase + c];
    const float hz = gh[gbase + CC + c];
    const float hn = gh[gbase + 2 * CC + c];

    const float h = __half2float(hhi_in[idx]) + __half2float(hlo_in[idx]);

    const float rg = 1.0f / (1.0f + __expf(-(xr + hr)));
    const float zg = 1.0f / (1.0f + __expf(-(xz + hz)));
    const float ng = tanhf(xn + rg * hn);
    const float hnew = (1.0f - zg) * ng + zg * h;

    if (isLast) {
        outF[idx] = hnew * mask[r];
    } else {
        const __half hb = __float2half_rn(hnew);
        hhi_out[idx] = hb;
        hlo_out[idx] = __float2half_rn(hnew - __half2float(hb));
    }
}

// ===========================================================================
#define SMEM_BIG   (3 * (32768 + 2 * 16384))         // 192 KB (adj 3-stage / gate 2-stage)
#define SMEM_HW    (2 * 4 * 16384)                   // 128 KB

extern "C" void kernel_launch(void* const* d_in, const int* in_sizes, int n_in,
                              void* d_out, int out_size)
{
    const float* x      = (const float*)d_in[0];
    const float* adj    = (const float*)d_in[1];
    const float* mask   = (const float*)d_in[2];
    const float* weight = (const float*)d_in[3];
    const float* w_ih   = (const float*)d_in[4];
    const float* w_hh   = (const float*)d_in[5];
    const float* b_ih   = (const float*)d_in[6];
    const float* b_hh   = (const float*)d_in[7];
    float* out = (float*)d_out;

    float *p_gx, *p_gh;
    __half *p_adjT, *p_hwhi, *p_hwlo, *p_mhi, *p_mlo;
    __half *p_hAhi, *p_hAlo, *p_hBhi, *p_hBlo;
    __half *p_wThi, *p_wTlo, *p_wihhi, *p_wihlo, *p_whhhi, *p_whhlo;
    cudaGetSymbolAddress((void**)&p_gx, g_gx);
    cudaGetSymbolAddress((void**)&p_gh, g_gh);
    cudaGetSymbolAddress((void**)&p_adjT, g_adjT);
    cudaGetSymbolAddress((void**)&p_hwhi, g_hwT_hi);
    cudaGetSymbolAddress((void**)&p_hwlo, g_hwT_lo);
    cudaGetSymbolAddress((void**)&p_mhi, g_mA_hi);
    cudaGetSymbolAddress((void**)&p_mlo, g_mA_lo);
    cudaGetSymbolAddress((void**)&p_hAhi, g_hA_hi);
    cudaGetSymbolAddress((void**)&p_hAlo, g_hA_lo);
    cudaGetSymbolAddress((void**)&p_hBhi, g_hB_hi);
    cudaGetSymbolAddress((void**)&p_hBlo, g_hB_lo);
    cudaGetSymbolAddress((void**)&p_wThi, g_wT_hi);
    cudaGetSymbolAddress((void**)&p_wTlo, g_wT_lo);
    cudaGetSymbolAddress((void**)&p_wihhi, g_wih_hi);
    cudaGetSymbolAddress((void**)&p_wihlo, g_wih_lo);
    cudaGetSymbolAddress((void**)&p_whhhi, g_whh_hi);
    cudaGetSymbolAddress((void**)&p_whhlo, g_whh_lo);

    cudaFuncSetAttribute(fused_adj_gh, cudaFuncAttributeMaxDynamicSharedMemorySize, SMEM_BIG);
    cudaFuncSetAttribute(gate_mma,     cudaFuncAttributeMaxDynamicSharedMemorySize, SMEM_BIG);
    cudaFuncSetAttribute(wmma2_hw,     cudaFuncAttributeMaxDynamicSharedMemorySize, SMEM_HW);

    // ---- once per call ----
    adj_transpose<<<dim3(NN / 32, NN / 32, BB), 256>>>(adj, p_adjT);
    wT_split<<<dim3(CC / 32, CC / 32, LL), 256>>>(weight, p_wThi, p_wTlo);
    split2<<<(LL * 3 * CC * CC) / 256, 256>>>(w_ih, p_wihhi, p_wihlo);
    split2<<<(LL * 3 * CC * CC) / 256, 256>>>(w_hh, p_whhhi, p_whhlo);
    split2<<<HSZ / 256, 256>>>(x, p_hAhi, p_hAlo);   // h0 = x

    __half* hs_hi[2] = { p_hAhi, p_hBhi };
    __half* hs_lo[2] = { p_hAlo, p_hBlo };

    for (int l = 0; l < LL; l++) {
        __half* chi = hs_hi[l & 1];
        __half* clo = hs_lo[l & 1];
        __half* nhi = hs_hi[(l + 1) & 1];
        __half* nlo = hs_lo[(l + 1) & 1];
        const long loffW = (long)l * CC * CC;
        const long loffG = (long)l * 3 * CC * CC;

        // 1) hwT[d][b*N+j] = sum_c WT[d][c] * h[j][c]   (3-product)
        wmma2_hw<<<dim3(ROWS / 128, 1, 1), 256, SMEM_HW>>>(
            p_wThi + loffW, p_wTlo + loffW, chi, clo,
            p_hwhi, p_hwlo, CC, CC, CC, ROWS);

        // 2) fused: m = adjT @ (hw_hi+hw_lo)  AND  gh = h @ w_hh^T + b_hh
        //    (gh CTAs fill the 20 SMs the 128 adj CTAs leave idle, then backfill)
        fused_adj_gh<<<512, 256, SMEM_BIG>>>(
            p_adjT, p_hwhi, p_hwlo, p_mhi, p_mlo,
            chi, clo, p_whhhi + loffG, p_whhlo + loffG,
            p_gh, b_hh + (long)l * 3 * CC);

        // 3) gx = m @ w_ih^T + b_ih
        gate_mma<<<dim3(3, ROWS / 256), 256, SMEM_BIG>>>(
            p_mhi, p_mlo, p_wihhi + loffG, p_wihlo + loffG,
            p_gx, b_ih + (long)l * 3 * CC);

        // 4) GRU elementwise
        gru_elem3<<<(ROWS * CC) / 256, 256>>>(
            p_gx, p_gh, chi, clo, nhi, nlo, out, mask, (l == LL - 1) ? 1 : 0);
    }
}